// round 15
// baseline (speedup 1.0000x reference)
#include <cuda_runtime.h>
#include <cstdint>
#include <cstddef>

#define Bq 32
#define Sq 100
#define Tq 100
#define Eq 512
#define Hq 512
#define G4 2048   // 4H
#define H2 1024   // 2H
#define H3 1536   // 3H
#define VTq 32000
#define NB 148    // persistent grid size (<= SM count, co-resident guaranteed)

// ---------------- scratch (static device globals; no allocation) ----------------
__device__ float g_xsrc[Sq * Bq * Eq];
__device__ float g_Xf[Sq * Bq * G4];
__device__ float g_Xb[Sq * Bq * G4];
__device__ float g_h[2][2][Bq][Hq];               // [slot][dir][b][u] encoder h ping-pong
__device__ float g_encout[Bq][Sq][H2];
__device__ float g_encT[Bq][H2][Sq];
__device__ float g_P[(size_t)Bq * Sq * H3];
__device__ float g_temb[Bq][Tq][Eq];
__device__ float g_temb_tb[Tq * Bq * Eq];
__device__ float g_Xdec[Tq * Bq * G4];
__device__ float g_hd[2][Bq][Hq];                 // decoder h ping-pong
__device__ float g_cd[Bq][Hq];                    // decoder initial c
__device__ float g_Qp[Bq][H3];                    // Q projection
__device__ float g_ctxs[Tq][Bq][H2];
__device__ float g_decs[Tq][Bq][Hq];
__device__ float g_clsin[(size_t)Bq * Tq * 2048];
__device__ float g_hid[(size_t)Bq * Tq * H2];

__device__ unsigned g_cnt = 0;
__device__ unsigned g_gen = 0;

__device__ __forceinline__ float sigf(float x) { return 1.f / (1.f + __expf(-x)); }

__device__ __forceinline__ uint32_t f2tf(float x) {
    uint32_t r;
    asm("cvt.rna.tf32.f32 %0, %1;" : "=r"(r) : "f"(x));
    return r;
}

__device__ __forceinline__ void cpa16(void* dst, const void* src) {
    uint32_t d = (uint32_t)__cvta_generic_to_shared(dst);
    asm volatile("cp.async.ca.shared.global [%0], [%1], 16;\n" :: "r"(d), "l"(src));
}
#define CPA_COMMIT() asm volatile("cp.async.commit_group;\n" ::: "memory")
#define CPA_WAIT0()  asm volatile("cp.async.wait_group 0;\n" ::: "memory")

// ---- fence-free grid barrier (no MEMBAR.GPU / CCTL.IVALL) ----
// All cross-block mutable data is written with plain STG (write-through to L2)
// and read with __ldcg (L2), so no L1 invalidation is needed; acq_rel atomics
// provide the ordering chain.
__device__ __forceinline__ unsigned ld_acq(unsigned* p) {
    unsigned v;
    asm volatile("ld.acquire.gpu.u32 %0, [%1];" : "=r"(v) : "l"(p));
    return v;
}
__device__ __forceinline__ void st_rel(unsigned* p, unsigned v) {
    asm volatile("st.release.gpu.u32 [%0], %1;" :: "l"(p), "r"(v));
}
__device__ __forceinline__ void st_rlx(unsigned* p, unsigned v) {
    asm volatile("st.relaxed.gpu.u32 [%0], %1;" :: "l"(p), "r"(v));
}
__device__ __forceinline__ unsigned add_acqrel(unsigned* p, unsigned v) {
    unsigned o;
    asm volatile("atom.add.acq_rel.gpu.u32 %0, [%1], %2;" : "=r"(o) : "l"(p), "r"(v));
    return o;
}

__device__ __forceinline__ void gridbar(unsigned& lg) {
    __syncthreads();
    if (threadIdx.x == 0) {
        lg++;
        if (add_acqrel(&g_cnt, 1u) == NB - 1) {
            st_rlx(&g_cnt, 0u);
            st_rel(&g_gen, lg);
        } else {
            while ((int)(ld_acq(&g_gen) - lg) < 0) __nanosleep(40);
        }
    }
    __syncthreads();
}

// ---------------- gathers ----------------
__global__ void k_gather_src(const int* __restrict__ src, const float* __restrict__ emb) {
    int m = blockIdx.x;            // m = s*B + b
    int s = m / Bq, b = m % Bq;
    int idx = src[b * Sq + s];
    float4 v = ((const float4*)(emb + (size_t)idx * Eq))[threadIdx.x];
    ((float4*)(g_xsrc + (size_t)m * Eq))[threadIdx.x] = v;
}

__global__ void k_gather_tgt(const int* __restrict__ tgt, const float* __restrict__ emb) {
    int m = blockIdx.x;            // m = b*T + t
    int b = m / Tq, t = m % Tq;
    int idx = tgt[m];
    float4 v = ((const float4*)(emb + (size_t)idx * Eq))[threadIdx.x];
    ((float4*)(&g_temb[b][t][0]))[threadIdx.x] = v;
    ((float4*)(g_temb_tb + ((size_t)t * Bq + b) * Eq))[threadIdx.x] = v;
}

// ---------------- tf32 tensor-core GEMM with cp.async double buffering ----------------
#define SSTR 20
__global__ void __launch_bounds__(256, 2) k_mma(
    const float* __restrict__ A, int lda,
    const float* __restrict__ W, int ldw,
    const float* __restrict__ bias1, const float* __restrict__ bias2,
    float* __restrict__ C, int ldc,
    int M, int N, int K, int do_relu)
{
    __shared__ float Asf[2][128 * SSTR];
    __shared__ float Wsf[2][128 * SSTR];
    int tid = threadIdx.x;
    int bm = blockIdx.x * 128, bn = blockIdx.y * 128;

    int warp = tid >> 5, lane = tid & 31;
    int wm = warp & 1, wn = warp >> 1;
    int grp = lane >> 2, qid = lane & 3;

    int l_row0 = (tid * 2) >> 2, l_q0 = (tid * 2) & 3;
    int l_row1 = (tid * 2 + 1) >> 2, l_q1 = (tid * 2 + 1) & 3;

    float acc[4][4][4];
#pragma unroll
    for (int i = 0; i < 4; i++)
#pragma unroll
        for (int j = 0; j < 4; j++)
#pragma unroll
            for (int r = 0; r < 4; r++) acc[i][j][r] = 0.f;

    cpa16(&Asf[0][l_row0 * SSTR + l_q0 * 4], A + (size_t)(bm + l_row0) * lda + l_q0 * 4);
    cpa16(&Wsf[0][l_row0 * SSTR + l_q0 * 4], W + (size_t)(bn + l_row0) * ldw + l_q0 * 4);
    cpa16(&Asf[0][l_row1 * SSTR + l_q1 * 4], A + (size_t)(bm + l_row1) * lda + l_q1 * 4);
    cpa16(&Wsf[0][l_row1 * SSTR + l_q1 * 4], W + (size_t)(bn + l_row1) * ldw + l_q1 * 4);
    CPA_COMMIT();

    int nt = K >> 4;
    for (int kt = 0; kt < nt; kt++) {
        int cur = kt & 1;
        CPA_WAIT0();
        __syncthreads();
        if (kt + 1 < nt) {
            int k0 = (kt + 1) << 4;
            int nx = cur ^ 1;
            cpa16(&Asf[nx][l_row0 * SSTR + l_q0 * 4], A + (size_t)(bm + l_row0) * lda + k0 + l_q0 * 4);
            cpa16(&Wsf[nx][l_row0 * SSTR + l_q0 * 4], W + (size_t)(bn + l_row0) * ldw + k0 + l_q0 * 4);
            cpa16(&Asf[nx][l_row1 * SSTR + l_q1 * 4], A + (size_t)(bm + l_row1) * lda + k0 + l_q1 * 4);
            cpa16(&Wsf[nx][l_row1 * SSTR + l_q1 * 4], W + (size_t)(bn + l_row1) * ldw + k0 + l_q1 * 4);
            CPA_COMMIT();
        }
#pragma unroll
        for (int kf = 0; kf < 2; kf++) {
            int kb = kf * 8;
            uint32_t a[4][4], b[4][2];
#pragma unroll
            for (int mf = 0; mf < 4; mf++) {
                int rb = (wm * 64 + mf * 16) * SSTR + kb;
                a[mf][0] = f2tf(Asf[cur][rb + grp * SSTR + qid]);
                a[mf][1] = f2tf(Asf[cur][rb + (grp + 8) * SSTR + qid]);
                a[mf][2] = f2tf(Asf[cur][rb + grp * SSTR + qid + 4]);
                a[mf][3] = f2tf(Asf[cur][rb + (grp + 8) * SSTR + qid + 4]);
            }
#pragma unroll
            for (int nf = 0; nf < 4; nf++) {
                int cb = (wn * 32 + nf * 8 + grp) * SSTR + kb;
                b[nf][0] = f2tf(Wsf[cur][cb + qid]);
                b[nf][1] = f2tf(Wsf[cur][cb + qid + 4]);
            }
#pragma unroll
            for (int mf = 0; mf < 4; mf++)
#pragma unroll
                for (int nf = 0; nf < 4; nf++) {
                    asm volatile(
                        "mma.sync.aligned.m16n8k8.row.col.f32.tf32.tf32.f32 "
                        "{%0,%1,%2,%3}, {%4,%5,%6,%7}, {%8,%9}, {%0,%1,%2,%3};\n"
                        : "+f"(acc[mf][nf][0]), "+f"(acc[mf][nf][1]),
                          "+f"(acc[mf][nf][2]), "+f"(acc[mf][nf][3])
                        : "r"(a[mf][0]), "r"(a[mf][1]), "r"(a[mf][2]), "r"(a[mf][3]),
                          "r"(b[nf][0]), "r"(b[nf][1]));
                }
        }
        __syncthreads();
    }

#pragma unroll
    for (int nf = 0; nf < 4; nf++) {
        int col = bn + wn * 32 + nf * 8 + qid * 2;
        float b0 = bias1[col], b1 = bias1[col + 1];
        if (bias2) { b0 += bias2[col]; b1 += bias2[col + 1]; }
#pragma unroll
        for (int mf = 0; mf < 4; mf++) {
            int row = bm + wm * 64 + mf * 16 + grp;
            float v0 = acc[mf][nf][0] + b0, v1 = acc[mf][nf][1] + b1;
            float v2 = acc[mf][nf][2] + b0, v3 = acc[mf][nf][3] + b1;
            if (do_relu) {
                v0 = fmaxf(v0, 0.f); v1 = fmaxf(v1, 0.f);
                v2 = fmaxf(v2, 0.f); v3 = fmaxf(v3, 0.f);
            }
            *(float2*)&C[(size_t)row * ldc + col] = make_float2(v0, v1);
            *(float2*)&C[(size_t)(row + 8) * ldc + col] = make_float2(v2, v3);
        }
    }
}

// ======== 4x4-tile 32x32xK block matmul helpers (persistent loops) ========
#define SAC(kg, r, b) sac[((kg) * 32 + (r)) * 33 + (b)]

__device__ __forceinline__ void mm4x4(const float (&Ws)[4][32][36], const float (&Xs)[4][32][36],
                                      int kg, int rx, int bx, float (&acc)[4][4]) {
#pragma unroll
    for (int kq = 0; kq < 8; kq++) {
        float4 w0 = *(const float4*)&Ws[kg][rx][kq * 4];
        float4 w1 = *(const float4*)&Ws[kg][rx + 8][kq * 4];
        float4 w2 = *(const float4*)&Ws[kg][rx + 16][kq * 4];
        float4 w3 = *(const float4*)&Ws[kg][rx + 24][kq * 4];
        float4 x0 = *(const float4*)&Xs[kg][bx][kq * 4];
        float4 x1 = *(const float4*)&Xs[kg][bx + 8][kq * 4];
        float4 x2 = *(const float4*)&Xs[kg][bx + 16][kq * 4];
        float4 x3 = *(const float4*)&Xs[kg][bx + 24][kq * 4];
        float4 wv[4] = {w0, w1, w2, w3};
        float4 xv[4] = {x0, x1, x2, x3};
#pragma unroll
        for (int i = 0; i < 4; i++)
#pragma unroll
            for (int j = 0; j < 4; j++)
                acc[i][j] += wv[i].x * xv[j].x + wv[i].y * xv[j].y
                           + wv[i].z * xv[j].z + wv[i].w * xv[j].w;
    }
}

// ---------------- persistent encoder loop ----------------
__global__ void __launch_bounds__(256) k_enc_loop(const float* __restrict__ Whh_f,
                                                  const float* __restrict__ Whh_b) {
    __shared__ float Ws[4][32][36];
    __shared__ float Xs[4][32][36];
    __shared__ float c_s[8][32];
    float* sac = &Ws[0][0][0];
    int tid = threadIdx.x, bid = blockIdx.x;
    unsigned lg = ld_acq(&g_gen);   // consistent base: gen can't advance before all arrive

    for (int i = bid * 256 + tid; i < 2 * Bq * Hq; i += NB * 256)
        ((float*)g_h[0])[i] = 0.f;
    c_s[tid >> 5][tid & 31] = 0.f;
    gridbar(lg);

    bool active = bid < 128;
    int d = bid >> 6;
    int u0 = (bid & 63) * 8;
    const float* W = d ? Whh_b : Whh_f;
    const float* X = d ? g_Xb : g_Xf;
    int kg = tid >> 6, t64 = tid & 63, rx = t64 >> 3, bx = t64 & 7;

    for (int s = 0; s < Sq; s++) {
        int slot = s & 1;
        if (active) {
            float acc[4][4];
#pragma unroll
            for (int i = 0; i < 4; i++)
#pragma unroll
                for (int j = 0; j < 4; j++) acc[i][j] = 0.f;

            for (int c = 0; c < 4; c++) {
#pragma unroll
                for (int i = 0; i < 4; i++) {
                    int idx = tid * 4 + i;
                    int kgs = idx >> 8, r = (idx >> 3) & 31, q = idx & 7;
                    int k = kgs * 128 + c * 32 + q * 4;
                    int grow = ((r >> 3) << 9) + u0 + (r & 7);
                    *(float4*)&Ws[kgs][r][q * 4] = *(const float4*)(W + (size_t)grow * Hq + k);
                    *(float4*)&Xs[kgs][r][q * 4] = __ldcg((const float4*)&g_h[slot][d][r][k]);
                }
                __syncthreads();
                mm4x4(Ws, Xs, kg, rx, bx, acc);
                __syncthreads();
            }
#pragma unroll
            for (int i = 0; i < 4; i++)
#pragma unroll
                for (int j = 0; j < 4; j++)
                    SAC(kg, rx + 8 * i, bx + 8 * j) = acc[i][j];
            __syncthreads();
            int uj = tid >> 5, b = tid & 31;
            int seff = d ? (Sq - 1 - s) : s;
            const float* Xp = X + ((size_t)seff * Bq + b) * G4;
            int u = u0 + uj;
            float gi = Xp[u], gf = Xp[512 + u], gg = Xp[1024 + u], go = Xp[1536 + u];
#pragma unroll
            for (int k2 = 0; k2 < 4; k2++) {
                gi += SAC(k2, uj, b);
                gf += SAC(k2, 8 + uj, b);
                gg += SAC(k2, 16 + uj, b);
                go += SAC(k2, 24 + uj, b);
            }
            float c = c_s[uj][b];
            c = sigf(gf) * c + sigf(gi) * tanhf(gg);
            float h = sigf(go) * tanhf(c);
            c_s[uj][b] = c;
            g_h[slot ^ 1][d][b][u] = h;
            g_encout[b][seff][(d << 9) + u] = h;
            g_encT[b][(d << 9) + u][seff] = h;
            if (d == 0 && s == Sq - 1) {
                g_hd[0][b][u] = h;
                g_cd[b][u] = c;
            }
        }
        gridbar(lg);
    }
}

// ---------------- persistent decoder loop ----------------
// per step (3 barriers): A qproj(48 blks, full K=512) | BC scores+softmax+ctx(32 blks)
//                        DE gates GEMM + LSTM (64 blks, full K=1536)
__global__ void __launch_bounds__(256) k_dec_loop(
    const float* __restrict__ att1_W, const float* __restrict__ att2_W,
    const float* __restrict__ dWih, const float* __restrict__ dWhh)
{
    __shared__ float Ws[4][32][36];
    __shared__ float Xs[4][32][36];
    __shared__ float a2s[H3];
    __shared__ float sw[128];
    __shared__ float c_s[8][32];
    float* sac = &Ws[0][0][0];
    int tid = threadIdx.x, bid = blockIdx.x;
    int kg = tid >> 6, t64 = tid & 63, rx = t64 >> 3, bx = t64 & 7;
    unsigned lg = ld_acq(&g_gen);

    for (int j = tid; j < H3; j += 256) a2s[j] = att2_W[j];
    if (bid < 64) {
        int uj = tid >> 5, b = tid & 31;
        c_s[uj][b] = __ldcg(&g_cd[b][(bid << 3) + uj]);
    }
    gridbar(lg);

    for (int t = 0; t < Tq; t++) {
        int slot = t & 1;
        // ---- phase A: Qp[b][j] = h @ att1_W[:,1024:]^T  (48 blocks, full K=512) ----
        if (bid < 48) {
            int j0 = bid * 32;
            float acc[4][4];
#pragma unroll
            for (int i = 0; i < 4; i++)
#pragma unroll
                for (int j = 0; j < 4; j++) acc[i][j] = 0.f;
            for (int c = 0; c < 4; c++) {
#pragma unroll
                for (int i = 0; i < 4; i++) {
                    int idx = tid * 4 + i;
                    int kgs = idx >> 8, r = (idx >> 3) & 31, q = idx & 7;
                    int k = kgs * 128 + c * 32 + q * 4;
                    *(float4*)&Ws[kgs][r][q * 4] =
                        *(const float4*)(att1_W + (size_t)(j0 + r) * H3 + H2 + k);
                    *(float4*)&Xs[kgs][r][q * 4] = __ldcg((const float4*)&g_hd[slot][r][k]);
                }
                __syncthreads();
                mm4x4(Ws, Xs, kg, rx, bx, acc);
                __syncthreads();
            }
#pragma unroll
            for (int i = 0; i < 4; i++)
#pragma unroll
                for (int j = 0; j < 4; j++)
                    SAC(kg, rx + 8 * i, bx + 8 * j) = acc[i][j];
            __syncthreads();
#pragma unroll
            for (int i = 0; i < 4; i++) {
                int cell = i * 256 + tid;
                int r = cell >> 5, b = cell & 31;
                g_Qp[b][j0 + r] = SAC(0, r, b) + SAC(1, r, b) + SAC(2, r, b) + SAC(3, r, b);
            }
        }
        gridbar(lg);
        // ---- phase BC: scores + softmax + ctx, one block per batch ----
        if (bid < 32) {
            int b = bid;
            int warp = tid >> 5, lane = tid & 31;
            for (int s = warp; s < Sq; s += 8) {
                const float* Pp = g_P + ((size_t)b * Sq + s) * H3;
                float acc = 0.f;
#pragma unroll
                for (int jj = 0; jj < 12; jj++) {
                    int j = jj * 128 + lane * 4;
                    float4 p = *(const float4*)(Pp + j);
                    float4 q0 = __ldcg((const float4*)&g_Qp[b][j]);
                    float4 a = *(const float4*)&a2s[j];
                    acc += fmaxf(p.x + q0.x, 0.f) * a.x
                         + fmaxf(p.y + q0.y, 0.f) * a.y
                         + fmaxf(p.z + q0.z, 0.f) * a.z
                         + fmaxf(p.w + q0.w, 0.f) * a.w;
                }
#pragma unroll
                for (int o = 16; o; o >>= 1) acc += __shfl_xor_sync(0xffffffffu, acc, o);
                if (!lane) sw[s] = acc;
            }
            __syncthreads();
            float mx = -1e30f;
#pragma unroll 4
            for (int i = 0; i < 100; i++) mx = fmaxf(mx, sw[i]);
            float ev = (tid < 100) ? __expf(sw[tid] - mx) : 0.f;
            __syncthreads();
            if (tid < 100) sw[tid] = ev;
            __syncthreads();
            float sum = 0.f;
#pragma unroll 4
            for (int i = 0; i < 100; i++) sum += sw[i];
            float inv = 1.f / sum;
#pragma unroll
            for (int kk = 0; kk < 4; kk++) {
                int k = kk * 256 + tid;
                const float* eT = &g_encT[b][k][0];
                float acc = 0.f;
#pragma unroll
                for (int s4 = 0; s4 < 100; s4 += 4) {
                    float4 e4 = *(const float4*)(eT + s4);
                    acc += sw[s4] * e4.x + sw[s4 + 1] * e4.y
                         + sw[s4 + 2] * e4.z + sw[s4 + 3] * e4.w;
                }
                g_ctxs[t][b][k] = acc * inv;
            }
        }
        gridbar(lg);
        // ---- phase DE: gate GEMM over K=1536 (ctx 1024 | h 512) + LSTM, 64 blocks ----
        if (bid < 64) {
            int u0 = bid * 8;
            float acc[4][4];
#pragma unroll
            for (int i = 0; i < 4; i++)
#pragma unroll
                for (int j = 0; j < 4; j++) acc[i][j] = 0.f;
            for (int c = 0; c < 12; c++) {
#pragma unroll
                for (int i = 0; i < 4; i++) {
                    int idx = tid * 4 + i;
                    int kgs = idx >> 8, r = (idx >> 3) & 31, q = idx & 7;
                    int k = kgs * 384 + c * 32 + q * 4;
                    int grow = ((r >> 3) << 9) + u0 + (r & 7);
                    if (k < 1024) {
                        *(float4*)&Ws[kgs][r][q * 4] =
                            *(const float4*)(dWih + (size_t)grow * H3 + 512 + k);
                        *(float4*)&Xs[kgs][r][q * 4] = __ldcg((const float4*)&g_ctxs[t][r][k]);
                    } else {
                        *(float4*)&Ws[kgs][r][q * 4] =
                            *(const float4*)(dWhh + (size_t)grow * Hq + (k - 1024));
                        *(float4*)&Xs[kgs][r][q * 4] =
                            __ldcg((const float4*)&g_hd[slot][r][k - 1024]);
                    }
                }
                __syncthreads();
                mm4x4(Ws, Xs, kg, rx, bx, acc);
                __syncthreads();
            }
#pragma unroll
            for (int i = 0; i < 4; i++)
#pragma unroll
                for (int j = 0; j < 4; j++)
                    SAC(kg, rx + 8 * i, bx + 8 * j) = acc[i][j];
            __syncthreads();
            // epilogue: combine k-groups + LSTM update
            int uj = tid >> 5, b = tid & 31;
            int u = u0 + uj;
            const float* Xp = g_Xdec + ((size_t)t * Bq + b) * G4;
            float gi = Xp[u], gf = Xp[512 + u], gg = Xp[1024 + u], go = Xp[1536 + u];
#pragma unroll
            for (int k2 = 0; k2 < 4; k2++) {
                gi += SAC(k2, uj, b);
                gf += SAC(k2, 8 + uj, b);
                gg += SAC(k2, 16 + uj, b);
                go += SAC(k2, 24 + uj, b);
            }
            float c = c_s[uj][b];
            c = sigf(gf) * c + sigf(gi) * tanhf(gg);
            float h = sigf(go) * tanhf(c);
            c_s[uj][b] = c;
            g_hd[slot ^ 1][b][u] = h;
            g_decs[t][b][u] = h;
        }
        gridbar(lg);
    }
}

// ---------------- classifier input pack ----------------
__global__ void k_pack() {
    int m = blockIdx.x;            // m = b*T + t
    int b = m / Tq, t = m % Tq;
    int tid = threadIdx.x;         // 128
    float4* dst = (float4*)(g_clsin + (size_t)m * 2048);
    dst[tid]       = ((const float4*)&g_temb[b][t][0])[tid];
    dst[128 + tid] = ((const float4*)&g_ctxs[t][b][0])[tid];
    dst[256 + tid] = ((const float4*)&g_ctxs[t][b][0])[128 + tid];
    dst[384 + tid] = ((const float4*)&g_decs[t][b][0])[tid];
}

// ---------------- host ----------------
extern "C" void kernel_launch(void* const* d_in, const int* in_sizes, int n_in,
                              void* d_out, int out_size) {
    (void)in_sizes; (void)n_in; (void)out_size;
    const int*   src       = (const int*)d_in[0];
    const int*   tgt       = (const int*)d_in[1];
    const float* src_emb   = (const float*)d_in[2];
    const float* tgt_emb   = (const float*)d_in[3];
    const float* eWih_f    = (const float*)d_in[4];
    const float* eWhh_f    = (const float*)d_in[5];
    const float* ebih_f    = (const float*)d_in[6];
    const float* ebhh_f    = (const float*)d_in[7];
    const float* eWih_b    = (const float*)d_in[8];
    const float* eWhh_b    = (const float*)d_in[9];
    const float* ebih_b    = (const float*)d_in[10];
    const float* ebhh_b    = (const float*)d_in[11];
    const float* dWih      = (const float*)d_in[12];
    const float* dWhh      = (const float*)d_in[13];
    const float* dbih      = (const float*)d_in[14];
    const float* dbhh      = (const float*)d_in[15];
    const float* att1_W    = (const float*)d_in[16];
    const float* att1_b    = (const float*)d_in[17];
    const float* att2_W    = (const float*)d_in[18];
    const float* cls1_W    = (const float*)d_in[20];
    const float* cls1_b    = (const float*)d_in[21];
    const float* cls2_W    = (const float*)d_in[22];
    const float* cls2_b    = (const float*)d_in[23];
    float* out = (float*)d_out;

    float *p_xsrc, *p_Xf, *p_Xb, *p_encout, *p_P, *p_temb_tb, *p_Xdec, *p_clsin, *p_hid;
    cudaGetSymbolAddress((void**)&p_xsrc, g_xsrc);
    cudaGetSymbolAddress((void**)&p_Xf, g_Xf);
    cudaGetSymbolAddress((void**)&p_Xb, g_Xb);
    cudaGetSymbolAddress((void**)&p_encout, g_encout);
    cudaGetSymbolAddress((void**)&p_P, g_P);
    cudaGetSymbolAddress((void**)&p_temb_tb, g_temb_tb);
    cudaGetSymbolAddress((void**)&p_Xdec, g_Xdec);
    cudaGetSymbolAddress((void**)&p_clsin, g_clsin);
    cudaGetSymbolAddress((void**)&p_hid, g_hid);

    k_gather_src<<<Sq * Bq, 128>>>(src, src_emb);
    k_gather_tgt<<<Bq * Tq, 128>>>(tgt, tgt_emb);

    // encoder input gates
    k_mma<<<dim3(25, 16), 256>>>(p_xsrc, Eq, eWih_f, Eq, ebih_f, ebhh_f,
                                 p_Xf, G4, Sq * Bq, G4, Eq, 0);
    k_mma<<<dim3(25, 16), 256>>>(p_xsrc, Eq, eWih_b, Eq, ebih_b, ebhh_b,
                                 p_Xb, G4, Sq * Bq, G4, Eq, 0);

    // persistent encoder (100 steps, 1 launch)
    k_enc_loop<<<NB, 256>>>(eWhh_f, eWhh_b);

    // attention layer-1 enc part (hoisted)
    k_mma<<<dim3(25, 12), 256>>>(p_encout, H2, att1_W, H3, att1_b, (const float*)nullptr,
                                 p_P, H3, Bq * Sq, H3, H2, 0);

    // decoder input gates (embedding part)
    k_mma<<<dim3(25, 16), 256>>>(p_temb_tb, Eq, dWih, H3, dbih, dbhh,
                                 p_Xdec, G4, Tq * Bq, G4, Eq, 0);

    // persistent decoder (100 steps, 1 launch)
    k_dec_loop<<<NB, 256>>>(att1_W, att2_W, dWih, dWhh);

    k_pack<<<Bq * Tq, 128>>>();

    // classifier
    k_mma<<<dim3(25, 8), 256>>>(p_clsin, 2048, cls1_W, 2048, cls1_b, (const float*)nullptr,
                                p_hid, H2, Bq * Tq, H2, 2048, 1);
    k_mma<<<dim3(25, 250), 256>>>(p_hid, H2, cls2_W, H2, cls2_b, (const float*)nullptr,
                                  out, VTq, Bq * Tq, VTq, H2, 0);
}

// round 16
// speedup vs baseline: 1.0004x; 1.0004x over previous
#include <cuda_runtime.h>
#include <cstdint>
#include <cstddef>

#define Bq 32
#define Sq 100
#define Tq 100
#define Eq 512
#define Hq 512
#define G4 2048   // 4H
#define H2 1024   // 2H
#define H3 1536   // 3H
#define VTq 32000
#define NB 148    // persistent grid size (<= SM count, co-resident guaranteed)

// ---------------- scratch (static device globals; no allocation) ----------------
__device__ float g_xsrc[Sq * Bq * Eq];
__device__ float g_Xf[Sq * Bq * G4];
__device__ float g_Xb[Sq * Bq * G4];
__device__ float g_h[2][2][Bq][Hq];               // [slot][dir][b][u] encoder h ping-pong
__device__ float g_encout[Bq][Sq][H2];
__device__ float g_encT[Bq][H2][Sq];
__device__ float g_P[(size_t)Bq * Sq * H3];
__device__ float g_temb[Bq][Tq][Eq];
__device__ float g_temb_tb[Tq * Bq * Eq];
__device__ float g_Xdec[Tq * Bq * G4];
__device__ float g_hd[2][Bq][Hq];                 // decoder h ping-pong
__device__ float g_cd[Bq][Hq];                    // decoder initial c
__device__ float g_Qp[Bq][H3];                    // Q projection
__device__ float g_ctxs[Tq][Bq][H2];
__device__ float g_decs[Tq][Bq][Hq];
__device__ float g_clsin[(size_t)Bq * Tq * 2048];
__device__ float g_hid[(size_t)Bq * Tq * H2];

__device__ unsigned g_cnt = 0;
__device__ unsigned g_gen = 0;

__device__ __forceinline__ float sigf(float x) { return 1.f / (1.f + __expf(-x)); }

__device__ __forceinline__ uint32_t f2tf(float x) {
    uint32_t r;
    asm("cvt.rna.tf32.f32 %0, %1;" : "=r"(r) : "f"(x));
    return r;
}

__device__ __forceinline__ void cpa16(void* dst, const void* src) {
    uint32_t d = (uint32_t)__cvta_generic_to_shared(dst);
    asm volatile("cp.async.ca.shared.global [%0], [%1], 16;\n" :: "r"(d), "l"(src));
}
#define CPA_COMMIT() asm volatile("cp.async.commit_group;\n" ::: "memory")
#define CPA_WAIT0()  asm volatile("cp.async.wait_group 0;\n" ::: "memory")

// ---- fence-free grid barrier (no MEMBAR.GPU / CCTL.IVALL) ----
// All cross-block mutable data is written with plain STG (write-through to L2)
// and read with __ldcg (L2), so no L1 invalidation is needed; acq_rel atomics
// provide the ordering chain.
__device__ __forceinline__ unsigned ld_acq(unsigned* p) {
    unsigned v;
    asm volatile("ld.acquire.gpu.u32 %0, [%1];" : "=r"(v) : "l"(p));
    return v;
}
__device__ __forceinline__ void st_rel(unsigned* p, unsigned v) {
    asm volatile("st.release.gpu.u32 [%0], %1;" :: "l"(p), "r"(v));
}
__device__ __forceinline__ void st_rlx(unsigned* p, unsigned v) {
    asm volatile("st.relaxed.gpu.u32 [%0], %1;" :: "l"(p), "r"(v));
}
__device__ __forceinline__ unsigned add_acqrel(unsigned* p, unsigned v) {
    unsigned o;
    asm volatile("atom.add.acq_rel.gpu.u32 %0, [%1], %2;" : "=r"(o) : "l"(p), "r"(v));
    return o;
}

__device__ __forceinline__ void gridbar(unsigned& lg) {
    __syncthreads();
    if (threadIdx.x == 0) {
        lg++;
        if (add_acqrel(&g_cnt, 1u) == NB - 1) {
            st_rlx(&g_cnt, 0u);
            st_rel(&g_gen, lg);
        } else {
            while ((int)(ld_acq(&g_gen) - lg) < 0) __nanosleep(40);
        }
    }
    __syncthreads();
}

// ---------------- gathers ----------------
__global__ void k_gather_src(const int* __restrict__ src, const float* __restrict__ emb) {
    int m = blockIdx.x;            // m = s*B + b
    int s = m / Bq, b = m % Bq;
    int idx = src[b * Sq + s];
    float4 v = ((const float4*)(emb + (size_t)idx * Eq))[threadIdx.x];
    ((float4*)(g_xsrc + (size_t)m * Eq))[threadIdx.x] = v;
}

__global__ void k_gather_tgt(const int* __restrict__ tgt, const float* __restrict__ emb) {
    int m = blockIdx.x;            // m = b*T + t
    int b = m / Tq, t = m % Tq;
    int idx = tgt[m];
    float4 v = ((const float4*)(emb + (size_t)idx * Eq))[threadIdx.x];
    ((float4*)(&g_temb[b][t][0]))[threadIdx.x] = v;
    ((float4*)(g_temb_tb + ((size_t)t * Bq + b) * Eq))[threadIdx.x] = v;
}

// ---------------- tf32 tensor-core GEMM with cp.async double buffering ----------------
#define SSTR 20
__global__ void __launch_bounds__(256, 2) k_mma(
    const float* __restrict__ A, int lda,
    const float* __restrict__ W, int ldw,
    const float* __restrict__ bias1, const float* __restrict__ bias2,
    float* __restrict__ C, int ldc,
    int M, int N, int K, int do_relu)
{
    __shared__ float Asf[2][128 * SSTR];
    __shared__ float Wsf[2][128 * SSTR];
    int tid = threadIdx.x;
    int bm = blockIdx.x * 128, bn = blockIdx.y * 128;

    int warp = tid >> 5, lane = tid & 31;
    int wm = warp & 1, wn = warp >> 1;
    int grp = lane >> 2, qid = lane & 3;

    int l_row0 = (tid * 2) >> 2, l_q0 = (tid * 2) & 3;
    int l_row1 = (tid * 2 + 1) >> 2, l_q1 = (tid * 2 + 1) & 3;

    float acc[4][4][4];
#pragma unroll
    for (int i = 0; i < 4; i++)
#pragma unroll
        for (int j = 0; j < 4; j++)
#pragma unroll
            for (int r = 0; r < 4; r++) acc[i][j][r] = 0.f;

    cpa16(&Asf[0][l_row0 * SSTR + l_q0 * 4], A + (size_t)(bm + l_row0) * lda + l_q0 * 4);
    cpa16(&Wsf[0][l_row0 * SSTR + l_q0 * 4], W + (size_t)(bn + l_row0) * ldw + l_q0 * 4);
    cpa16(&Asf[0][l_row1 * SSTR + l_q1 * 4], A + (size_t)(bm + l_row1) * lda + l_q1 * 4);
    cpa16(&Wsf[0][l_row1 * SSTR + l_q1 * 4], W + (size_t)(bn + l_row1) * ldw + l_q1 * 4);
    CPA_COMMIT();

    int nt = K >> 4;
    for (int kt = 0; kt < nt; kt++) {
        int cur = kt & 1;
        CPA_WAIT0();
        __syncthreads();
        if (kt + 1 < nt) {
            int k0 = (kt + 1) << 4;
            int nx = cur ^ 1;
            cpa16(&Asf[nx][l_row0 * SSTR + l_q0 * 4], A + (size_t)(bm + l_row0) * lda + k0 + l_q0 * 4);
            cpa16(&Wsf[nx][l_row0 * SSTR + l_q0 * 4], W + (size_t)(bn + l_row0) * ldw + k0 + l_q0 * 4);
            cpa16(&Asf[nx][l_row1 * SSTR + l_q1 * 4], A + (size_t)(bm + l_row1) * lda + k0 + l_q1 * 4);
            cpa16(&Wsf[nx][l_row1 * SSTR + l_q1 * 4], W + (size_t)(bn + l_row1) * ldw + k0 + l_q1 * 4);
            CPA_COMMIT();
        }
#pragma unroll
        for (int kf = 0; kf < 2; kf++) {
            int kb = kf * 8;
            uint32_t a[4][4], b[4][2];
#pragma unroll
            for (int mf = 0; mf < 4; mf++) {
                int rb = (wm * 64 + mf * 16) * SSTR + kb;
                a[mf][0] = f2tf(Asf[cur][rb + grp * SSTR + qid]);
                a[mf][1] = f2tf(Asf[cur][rb + (grp + 8) * SSTR + qid]);
                a[mf][2] = f2tf(Asf[cur][rb + grp * SSTR + qid + 4]);
                a[mf][3] = f2tf(Asf[cur][rb + (grp + 8) * SSTR + qid + 4]);
            }
#pragma unroll
            for (int nf = 0; nf < 4; nf++) {
                int cb = (wn * 32 + nf * 8 + grp) * SSTR + kb;
                b[nf][0] = f2tf(Wsf[cur][cb + qid]);
                b[nf][1] = f2tf(Wsf[cur][cb + qid + 4]);
            }
#pragma unroll
            for (int mf = 0; mf < 4; mf++)
#pragma unroll
                for (int nf = 0; nf < 4; nf++) {
                    asm volatile(
                        "mma.sync.aligned.m16n8k8.row.col.f32.tf32.tf32.f32 "
                        "{%0,%1,%2,%3}, {%4,%5,%6,%7}, {%8,%9}, {%0,%1,%2,%3};\n"
                        : "+f"(acc[mf][nf][0]), "+f"(acc[mf][nf][1]),
                          "+f"(acc[mf][nf][2]), "+f"(acc[mf][nf][3])
                        : "r"(a[mf][0]), "r"(a[mf][1]), "r"(a[mf][2]), "r"(a[mf][3]),
                          "r"(b[nf][0]), "r"(b[nf][1]));
                }
        }
        __syncthreads();
    }

#pragma unroll
    for (int nf = 0; nf < 4; nf++) {
        int col = bn + wn * 32 + nf * 8 + qid * 2;
        float b0 = bias1[col], b1 = bias1[col + 1];
        if (bias2) { b0 += bias2[col]; b1 += bias2[col + 1]; }
#pragma unroll
        for (int mf = 0; mf < 4; mf++) {
            int row = bm + wm * 64 + mf * 16 + grp;
            float v0 = acc[mf][nf][0] + b0, v1 = acc[mf][nf][1] + b1;
            float v2 = acc[mf][nf][2] + b0, v3 = acc[mf][nf][3] + b1;
            if (do_relu) {
                v0 = fmaxf(v0, 0.f); v1 = fmaxf(v1, 0.f);
                v2 = fmaxf(v2, 0.f); v3 = fmaxf(v3, 0.f);
            }
            *(float2*)&C[(size_t)row * ldc + col] = make_float2(v0, v1);
            *(float2*)&C[(size_t)(row + 8) * ldc + col] = make_float2(v2, v3);
        }
    }
}

// ======== 4x4-tile 32x32xK block matmul helpers (persistent loops) ========
#define SAC(kg, r, b) sac[((kg) * 32 + (r)) * 33 + (b)]

__device__ __forceinline__ void mm4x4(const float (&Ws)[4][32][36], const float (&Xs)[4][32][36],
                                      int kg, int rx, int bx, float (&acc)[4][4]) {
#pragma unroll
    for (int kq = 0; kq < 8; kq++) {
        float4 w0 = *(const float4*)&Ws[kg][rx][kq * 4];
        float4 w1 = *(const float4*)&Ws[kg][rx + 8][kq * 4];
        float4 w2 = *(const float4*)&Ws[kg][rx + 16][kq * 4];
        float4 w3 = *(const float4*)&Ws[kg][rx + 24][kq * 4];
        float4 x0 = *(const float4*)&Xs[kg][bx][kq * 4];
        float4 x1 = *(const float4*)&Xs[kg][bx + 8][kq * 4];
        float4 x2 = *(const float4*)&Xs[kg][bx + 16][kq * 4];
        float4 x3 = *(const float4*)&Xs[kg][bx + 24][kq * 4];
        float4 wv[4] = {w0, w1, w2, w3};
        float4 xv[4] = {x0, x1, x2, x3};
#pragma unroll
        for (int i = 0; i < 4; i++)
#pragma unroll
            for (int j = 0; j < 4; j++)
                acc[i][j] += wv[i].x * xv[j].x + wv[i].y * xv[j].y
                           + wv[i].z * xv[j].z + wv[i].w * xv[j].w;
    }
}

// ---------------- persistent encoder loop ----------------
__global__ void __launch_bounds__(256) k_enc_loop(const float* __restrict__ Whh_f,
                                                  const float* __restrict__ Whh_b) {
    __shared__ float Ws[4][32][36];
    __shared__ float Xs[4][32][36];
    __shared__ float c_s[8][32];
    float* sac = &Ws[0][0][0];
    int tid = threadIdx.x, bid = blockIdx.x;
    unsigned lg = ld_acq(&g_gen);   // consistent base: gen can't advance before all arrive

    for (int i = bid * 256 + tid; i < 2 * Bq * Hq; i += NB * 256)
        ((float*)g_h[0])[i] = 0.f;
    c_s[tid >> 5][tid & 31] = 0.f;
    gridbar(lg);

    bool active = bid < 128;
    int d = bid >> 6;
    int u0 = (bid & 63) * 8;
    const float* W = d ? Whh_b : Whh_f;
    const float* X = d ? g_Xb : g_Xf;
    int kg = tid >> 6, t64 = tid & 63, rx = t64 >> 3, bx = t64 & 7;

    for (int s = 0; s < Sq; s++) {
        int slot = s & 1;
        if (active) {
            float acc[4][4];
#pragma unroll
            for (int i = 0; i < 4; i++)
#pragma unroll
                for (int j = 0; j < 4; j++) acc[i][j] = 0.f;

            for (int c = 0; c < 4; c++) {
#pragma unroll
                for (int i = 0; i < 4; i++) {
                    int idx = tid * 4 + i;
                    int kgs = idx >> 8, r = (idx >> 3) & 31, q = idx & 7;
                    int k = kgs * 128 + c * 32 + q * 4;
                    int grow = ((r >> 3) << 9) + u0 + (r & 7);
                    *(float4*)&Ws[kgs][r][q * 4] = *(const float4*)(W + (size_t)grow * Hq + k);
                    *(float4*)&Xs[kgs][r][q * 4] = __ldcg((const float4*)&g_h[slot][d][r][k]);
                }
                __syncthreads();
                mm4x4(Ws, Xs, kg, rx, bx, acc);
                __syncthreads();
            }
#pragma unroll
            for (int i = 0; i < 4; i++)
#pragma unroll
                for (int j = 0; j < 4; j++)
                    SAC(kg, rx + 8 * i, bx + 8 * j) = acc[i][j];
            __syncthreads();
            int uj = tid >> 5, b = tid & 31;
            int seff = d ? (Sq - 1 - s) : s;
            const float* Xp = X + ((size_t)seff * Bq + b) * G4;
            int u = u0 + uj;
            float gi = Xp[u], gf = Xp[512 + u], gg = Xp[1024 + u], go = Xp[1536 + u];
#pragma unroll
            for (int k2 = 0; k2 < 4; k2++) {
                gi += SAC(k2, uj, b);
                gf += SAC(k2, 8 + uj, b);
                gg += SAC(k2, 16 + uj, b);
                go += SAC(k2, 24 + uj, b);
            }
            float c = c_s[uj][b];
            c = sigf(gf) * c + sigf(gi) * tanhf(gg);
            float h = sigf(go) * tanhf(c);
            c_s[uj][b] = c;
            g_h[slot ^ 1][d][b][u] = h;
            g_encout[b][seff][(d << 9) + u] = h;
            g_encT[b][(d << 9) + u][seff] = h;
            if (d == 0 && s == Sq - 1) {
                g_hd[0][b][u] = h;
                g_cd[b][u] = c;
            }
        }
        gridbar(lg);
    }
}

// ---------------- persistent decoder loop ----------------
// per step (3 barriers): A qproj(48 blks, full K=512) | BC scores+softmax+ctx(32 blks)
//                        DE gates GEMM + LSTM (64 blks, full K=1536)
__global__ void __launch_bounds__(256) k_dec_loop(
    const float* __restrict__ att1_W, const float* __restrict__ att2_W,
    const float* __restrict__ dWih, const float* __restrict__ dWhh)
{
    __shared__ float Ws[4][32][36];
    __shared__ float Xs[4][32][36];
    __shared__ float a2s[H3];
    __shared__ float sw[128];
    __shared__ float c_s[8][32];
    float* sac = &Ws[0][0][0];
    int tid = threadIdx.x, bid = blockIdx.x;
    int kg = tid >> 6, t64 = tid & 63, rx = t64 >> 3, bx = t64 & 7;
    unsigned lg = ld_acq(&g_gen);

    for (int j = tid; j < H3; j += 256) a2s[j] = att2_W[j];
    if (bid < 64) {
        int uj = tid >> 5, b = tid & 31;
        c_s[uj][b] = __ldcg(&g_cd[b][(bid << 3) + uj]);
    }
    gridbar(lg);

    for (int t = 0; t < Tq; t++) {
        int slot = t & 1;
        // ---- phase A: Qp[b][j] = h @ att1_W[:,1024:]^T  (48 blocks, full K=512) ----
        if (bid < 48) {
            int j0 = bid * 32;
            float acc[4][4];
#pragma unroll
            for (int i = 0; i < 4; i++)
#pragma unroll
                for (int j = 0; j < 4; j++) acc[i][j] = 0.f;
            for (int c = 0; c < 4; c++) {
#pragma unroll
                for (int i = 0; i < 4; i++) {
                    int idx = tid * 4 + i;
                    int kgs = idx >> 8, r = (idx >> 3) & 31, q = idx & 7;
                    int k = kgs * 128 + c * 32 + q * 4;
                    *(float4*)&Ws[kgs][r][q * 4] =
                        *(const float4*)(att1_W + (size_t)(j0 + r) * H3 + H2 + k);
                    *(float4*)&Xs[kgs][r][q * 4] = __ldcg((const float4*)&g_hd[slot][r][k]);
                }
                __syncthreads();
                mm4x4(Ws, Xs, kg, rx, bx, acc);
                __syncthreads();
            }
#pragma unroll
            for (int i = 0; i < 4; i++)
#pragma unroll
                for (int j = 0; j < 4; j++)
                    SAC(kg, rx + 8 * i, bx + 8 * j) = acc[i][j];
            __syncthreads();
#pragma unroll
            for (int i = 0; i < 4; i++) {
                int cell = i * 256 + tid;
                int r = cell >> 5, b = cell & 31;
                g_Qp[b][j0 + r] = SAC(0, r, b) + SAC(1, r, b) + SAC(2, r, b) + SAC(3, r, b);
            }
        }
        gridbar(lg);
        // ---- phase BC: scores + softmax + ctx, one block per batch ----
        if (bid < 32) {
            int b = bid;
            int warp = tid >> 5, lane = tid & 31;
            for (int s = warp; s < Sq; s += 8) {
                const float* Pp = g_P + ((size_t)b * Sq + s) * H3;
                float acc = 0.f;
#pragma unroll
                for (int jj = 0; jj < 12; jj++) {
                    int j = jj * 128 + lane * 4;
                    float4 p = *(const float4*)(Pp + j);
                    float4 q0 = __ldcg((const float4*)&g_Qp[b][j]);
                    float4 a = *(const float4*)&a2s[j];
                    acc += fmaxf(p.x + q0.x, 0.f) * a.x
                         + fmaxf(p.y + q0.y, 0.f) * a.y
                         + fmaxf(p.z + q0.z, 0.f) * a.z
                         + fmaxf(p.w + q0.w, 0.f) * a.w;
                }
#pragma unroll
                for (int o = 16; o; o >>= 1) acc += __shfl_xor_sync(0xffffffffu, acc, o);
                if (!lane) sw[s] = acc;
            }
            __syncthreads();
            float mx = -1e30f;
#pragma unroll 4
            for (int i = 0; i < 100; i++) mx = fmaxf(mx, sw[i]);
            float ev = (tid < 100) ? __expf(sw[tid] - mx) : 0.f;
            __syncthreads();
            if (tid < 100) sw[tid] = ev;
            __syncthreads();
            float sum = 0.f;
#pragma unroll 4
            for (int i = 0; i < 100; i++) sum += sw[i];
            float inv = 1.f / sum;
#pragma unroll
            for (int kk = 0; kk < 4; kk++) {
                int k = kk * 256 + tid;
                const float* eT = &g_encT[b][k][0];
                float acc = 0.f;
#pragma unroll
                for (int s4 = 0; s4 < 100; s4 += 4) {
                    float4 e4 = *(const float4*)(eT + s4);
                    acc += sw[s4] * e4.x + sw[s4 + 1] * e4.y
                         + sw[s4 + 2] * e4.z + sw[s4 + 3] * e4.w;
                }
                g_ctxs[t][b][k] = acc * inv;
            }
        }
        gridbar(lg);
        // ---- phase DE: gate GEMM over K=1536 (ctx 1024 | h 512) + LSTM, 64 blocks ----
        if (bid < 64) {
            int u0 = bid * 8;
            float acc[4][4];
#pragma unroll
            for (int i = 0; i < 4; i++)
#pragma unroll
                for (int j = 0; j < 4; j++) acc[i][j] = 0.f;
            for (int c = 0; c < 12; c++) {
#pragma unroll
                for (int i = 0; i < 4; i++) {
                    int idx = tid * 4 + i;
                    int kgs = idx >> 8, r = (idx >> 3) & 31, q = idx & 7;
                    int k = kgs * 384 + c * 32 + q * 4;
                    int grow = ((r >> 3) << 9) + u0 + (r & 7);
                    if (k < 1024) {
                        *(float4*)&Ws[kgs][r][q * 4] =
                            *(const float4*)(dWih + (size_t)grow * H3 + 512 + k);
                        *(float4*)&Xs[kgs][r][q * 4] = __ldcg((const float4*)&g_ctxs[t][r][k]);
                    } else {
                        *(float4*)&Ws[kgs][r][q * 4] =
                            *(const float4*)(dWhh + (size_t)grow * Hq + (k - 1024));
                        *(float4*)&Xs[kgs][r][q * 4] =
                            __ldcg((const float4*)&g_hd[slot][r][k - 1024]);
                    }
                }
                __syncthreads();
                mm4x4(Ws, Xs, kg, rx, bx, acc);
                __syncthreads();
            }
#pragma unroll
            for (int i = 0; i < 4; i++)
#pragma unroll
                for (int j = 0; j < 4; j++)
                    SAC(kg, rx + 8 * i, bx + 8 * j) = acc[i][j];
            __syncthreads();
            // epilogue: combine k-groups + LSTM update
            int uj = tid >> 5, b = tid & 31;
            int u = u0 + uj;
            const float* Xp = g_Xdec + ((size_t)t * Bq + b) * G4;
            float gi = Xp[u], gf = Xp[512 + u], gg = Xp[1024 + u], go = Xp[1536 + u];
#pragma unroll
            for (int k2 = 0; k2 < 4; k2++) {
                gi += SAC(k2, uj, b);
                gf += SAC(k2, 8 + uj, b);
                gg += SAC(k2, 16 + uj, b);
                go += SAC(k2, 24 + uj, b);
            }
            float c = c_s[uj][b];
            c = sigf(gf) * c + sigf(gi) * tanhf(gg);
            float h = sigf(go) * tanhf(c);
            c_s[uj][b] = c;
            g_hd[slot ^ 1][b][u] = h;
            g_decs[t][b][u] = h;
        }
        gridbar(lg);
    }
}

// ---------------- classifier input pack ----------------
__global__ void k_pack() {
    int m = blockIdx.x;            // m = b*T + t
    int b = m / Tq, t = m % Tq;
    int tid = threadIdx.x;         // 128
    float4* dst = (float4*)(g_clsin + (size_t)m * 2048);
    dst[tid]       = ((const float4*)&g_temb[b][t][0])[tid];
    dst[128 + tid] = ((const float4*)&g_ctxs[t][b][0])[tid];
    dst[256 + tid] = ((const float4*)&g_ctxs[t][b][0])[128 + tid];
    dst[384 + tid] = ((const float4*)&g_decs[t][b][0])[tid];
}

// ---------------- host ----------------
extern "C" void kernel_launch(void* const* d_in, const int* in_sizes, int n_in,
                              void* d_out, int out_size) {
    (void)in_sizes; (void)n_in; (void)out_size;
    const int*   src       = (const int*)d_in[0];
    const int*   tgt       = (const int*)d_in[1];
    const float* src_emb   = (const float*)d_in[2];
    const float* tgt_emb   = (const float*)d_in[3];
    const float* eWih_f    = (const float*)d_in[4];
    const float* eWhh_f    = (const float*)d_in[5];
    const float* ebih_f    = (const float*)d_in[6];
    const float* ebhh_f    = (const float*)d_in[7];
    const float* eWih_b    = (const float*)d_in[8];
    const float* eWhh_b    = (const float*)d_in[9];
    const float* ebih_b    = (const float*)d_in[10];
    const float* ebhh_b    = (const float*)d_in[11];
    const float* dWih      = (const float*)d_in[12];
    const float* dWhh      = (const float*)d_in[13];
    const float* dbih      = (const float*)d_in[14];
    const float* dbhh      = (const float*)d_in[15];
    const float* att1_W    = (const float*)d_in[16];
    const float* att1_b    = (const float*)d_in[17];
    const float* att2_W    = (const float*)d_in[18];
    const float* cls1_W    = (const float*)d_in[20];
    const float* cls1_b    = (const float*)d_in[21];
    const float* cls2_W    = (const float*)d_in[22];
    const float* cls2_b    = (const float*)d_in[23];
    float* out = (float*)d_out;

    float *p_xsrc, *p_Xf, *p_Xb, *p_encout, *p_P, *p_temb_tb, *p_Xdec, *p_clsin, *p_hid;
    cudaGetSymbolAddress((void**)&p_xsrc, g_xsrc);
    cudaGetSymbolAddress((void**)&p_Xf, g_Xf);
    cudaGetSymbolAddress((void**)&p_Xb, g_Xb);
    cudaGetSymbolAddress((void**)&p_encout, g_encout);
    cudaGetSymbolAddress((void**)&p_P, g_P);
    cudaGetSymbolAddress((void**)&p_temb_tb, g_temb_tb);
    cudaGetSymbolAddress((void**)&p_Xdec, g_Xdec);
    cudaGetSymbolAddress((void**)&p_clsin, g_clsin);
    cudaGetSymbolAddress((void**)&p_hid, g_hid);

    k_gather_src<<<Sq * Bq, 128>>>(src, src_emb);
    k_gather_tgt<<<Bq * Tq, 128>>>(tgt, tgt_emb);

    // encoder input gates
    k_mma<<<dim3(25, 16), 256>>>(p_xsrc, Eq, eWih_f, Eq, ebih_f, ebhh_f,
                                 p_Xf, G4, Sq * Bq, G4, Eq, 0);
    k_mma<<<dim3(25, 16), 256>>>(p_xsrc, Eq, eWih_b, Eq, ebih_b, ebhh_b,
                                 p_Xb, G4, Sq * Bq, G4, Eq, 0);

    // persistent encoder (100 steps, 1 launch)
    k_enc_loop<<<NB, 256>>>(eWhh_f, eWhh_b);

    // attention layer-1 enc part (hoisted)
    k_mma<<<dim3(25, 12), 256>>>(p_encout, H2, att1_W, H3, att1_b, (const float*)nullptr,
                                 p_P, H3, Bq * Sq, H3, H2, 0);

    // decoder input gates (embedding part)
    k_mma<<<dim3(25, 16), 256>>>(p_temb_tb, Eq, dWih, H3, dbih, dbhh,
                                 p_Xdec, G4, Tq * Bq, G4, Eq, 0);

    // persistent decoder (100 steps, 1 launch)
    k_dec_loop<<<NB, 256>>>(att1_W, att2_W, dWih, dWhh);

    k_pack<<<Bq * Tq, 128>>>();

    // classifier
    k_mma<<<dim3(25, 8), 256>>>(p_clsin, 2048, cls1_W, 2048, cls1_b, (const float*)nullptr,
                                p_hid, H2, Bq * Tq, H2, 2048, 1);
    k_mma<<<dim3(25, 250), 256>>>(p_hid, H2, cls2_W, H2, cls2_b, (const float*)nullptr,
                                  out, VTq, Bq * Tq, VTq, H2, 0);
}

// round 17
// speedup vs baseline: 1.1615x; 1.1610x over previous
#include <cuda_runtime.h>
#include <cstdint>
#include <cstddef>

#define Bq 32
#define Sq 100
#define Tq 100
#define Eq 512
#define Hq 512
#define G4 2048   // 4H
#define H2 1024   // 2H
#define H3 1536   // 3H
#define VTq 32000
#define NB 148    // persistent grid size (<= SM count, co-resident guaranteed)

// ---------------- scratch (static device globals; no allocation) ----------------
__device__ float g_xsrc[Sq * Bq * Eq];            // tf32 bits
__device__ float g_Xf[Sq * Bq * G4];
__device__ float g_Xb[Sq * Bq * G4];
__device__ float g_h[2][2][Bq][Hq];               // [slot][dir][b][u] encoder h ping-pong
__device__ float g_encout[Bq][Sq][H2];            // tf32 bits (feeds P GEMM only)
__device__ float g_encT[Bq][H2][Sq];              // fp32
__device__ float g_P[(size_t)Bq * Sq * H3];
__device__ float g_temb[Bq][Tq][Eq];              // fp32
__device__ float g_temb_tb[Tq * Bq * Eq];         // tf32 bits
__device__ float g_Xdec[Tq * Bq * G4];
__device__ float g_hd[2][Bq][Hq];                 // decoder h ping-pong
__device__ float g_cd[Bq][Hq];                    // decoder initial c
__device__ float g_Qp[2][Bq][H3];                 // Q projection k-split partials
__device__ float g_gpart[2][G4][Bq];              // lstm gate partials (k-split)
__device__ float g_ctxs[Tq][Bq][H2];
__device__ float g_decs[Tq][Bq][Hq];
__device__ float g_clsin[(size_t)Bq * Tq * 2048]; // tf32 bits
__device__ float g_hid[(size_t)Bq * Tq * H2];     // tf32 bits (cls1 out)

// tf32-converted weight copies (converted once per launch)
__device__ float g_wfT[G4 * Eq];
__device__ float g_wbT[G4 * Eq];
__device__ float g_dwT[G4 * Eq];                  // dWih[:, :512]
__device__ float g_a1T[(size_t)H3 * H2];          // att1_W[:, :1024]
__device__ float g_c1T[(size_t)H2 * 2048];
__device__ float g_c2T[(size_t)VTq * H2];

__device__ unsigned g_cnt = 0;
__device__ volatile unsigned g_gen = 0;

__device__ __forceinline__ float sigf(float x) { return 1.f / (1.f + __expf(-x)); }

__device__ __forceinline__ uint32_t f2tf(float x) {
    uint32_t r;
    asm("cvt.rna.tf32.f32 %0, %1;" : "=r"(r) : "f"(x));
    return r;
}
__device__ __forceinline__ float f2tff(float x) { return __uint_as_float(f2tf(x)); }

__device__ __forceinline__ void cpa16(void* dst, const void* src) {
    uint32_t d = (uint32_t)__cvta_generic_to_shared(dst);
    asm volatile("cp.async.ca.shared.global [%0], [%1], 16;\n" :: "r"(d), "l"(src));
}
#define CPA_COMMIT() asm volatile("cp.async.commit_group;\n" ::: "memory")
#define CPA_WAIT0()  asm volatile("cp.async.wait_group 0;\n" ::: "memory")

// software grid barrier: all NB blocks must participate (R14-proven version)
__device__ __forceinline__ void gridbar() {
    __syncthreads();
    __threadfence();                       // release my writes
    if (threadIdx.x == 0) {
        unsigned g = g_gen;
        if (atomicAdd(&g_cnt, 1u) == NB - 1) {
            atomicExch(&g_cnt, 0u);
            __threadfence();
            g_gen = g + 1;
        } else {
            while (g_gen == g) { }
        }
    }
    __syncthreads();
    __threadfence();                       // acquire
}

// ---------------- weight conversion: dst[r*cols+c] = tf32(src[r*srcld+c]) ----------------
__global__ void k_conv(float* __restrict__ dst, const float* __restrict__ src,
                       int cols, int srcld) {
    size_t i = ((size_t)blockIdx.x * 256 + threadIdx.x) * 4;
    size_t r = i / (size_t)cols;
    int c = (int)(i % (size_t)cols);
    float4 v = *(const float4*)(src + r * srcld + c);
    float4 o = make_float4(f2tff(v.x), f2tff(v.y), f2tff(v.z), f2tff(v.w));
    *(float4*)(dst + r * cols + c) = o;
}

// ---------------- gathers ----------------
__global__ void k_gather_src(const int* __restrict__ src, const float* __restrict__ emb) {
    int m = blockIdx.x;            // m = s*B + b
    int s = m / Bq, b = m % Bq;
    int idx = src[b * Sq + s];
    float4 v = ((const float4*)(emb + (size_t)idx * Eq))[threadIdx.x];
    float4 o = make_float4(f2tff(v.x), f2tff(v.y), f2tff(v.z), f2tff(v.w));
    ((float4*)(g_xsrc + (size_t)m * Eq))[threadIdx.x] = o;   // feeds GEMMs only
}

__global__ void k_gather_tgt(const int* __restrict__ tgt, const float* __restrict__ emb) {
    int m = blockIdx.x;            // m = b*T + t
    int b = m / Tq, t = m % Tq;
    int idx = tgt[m];
    float4 v = ((const float4*)(emb + (size_t)idx * Eq))[threadIdx.x];
    ((float4*)(&g_temb[b][t][0]))[threadIdx.x] = v;          // fp32 (pack converts)
    float4 o = make_float4(f2tff(v.x), f2tff(v.y), f2tff(v.z), f2tff(v.w));
    ((float4*)(g_temb_tb + ((size_t)t * Bq + b) * Eq))[threadIdx.x] = o;  // GEMM only
}

// ---------------- tf32 tensor-core GEMM, pre-converted inputs (no inner cvt) ----------------
// C[M,N] = act(A[M,K] @ W[N,K]^T + bias1 (+bias2)); A,W hold tf32 bit patterns.
// flags: bit0 = relu, bit1 = store output as tf32 bits.
#define SSTR 20
__global__ void __launch_bounds__(256, 2) k_mma(
    const float* __restrict__ A, int lda,
    const float* __restrict__ W, int ldw,
    const float* __restrict__ bias1, const float* __restrict__ bias2,
    float* __restrict__ C, int ldc,
    int M, int N, int K, int flags)
{
    __shared__ float Asf[2][128 * SSTR];
    __shared__ float Wsf[2][128 * SSTR];
    int tid = threadIdx.x;
    int bm = blockIdx.x * 128, bn = blockIdx.y * 128;

    int warp = tid >> 5, lane = tid & 31;
    int wm = warp & 1, wn = warp >> 1;
    int grp = lane >> 2, qid = lane & 3;

    int l_row0 = (tid * 2) >> 2, l_q0 = (tid * 2) & 3;
    int l_row1 = (tid * 2 + 1) >> 2, l_q1 = (tid * 2 + 1) & 3;

    const float* Ar0 = A + (size_t)(bm + l_row0) * lda + l_q0 * 4;
    const float* Wr0 = W + (size_t)(bn + l_row0) * ldw + l_q0 * 4;
    const float* Ar1 = A + (size_t)(bm + l_row1) * lda + l_q1 * 4;
    const float* Wr1 = W + (size_t)(bn + l_row1) * ldw + l_q1 * 4;

    float acc[4][4][4];
#pragma unroll
    for (int i = 0; i < 4; i++)
#pragma unroll
        for (int j = 0; j < 4; j++)
#pragma unroll
            for (int r = 0; r < 4; r++) acc[i][j][r] = 0.f;

    cpa16(&Asf[0][l_row0 * SSTR + l_q0 * 4], Ar0);
    cpa16(&Wsf[0][l_row0 * SSTR + l_q0 * 4], Wr0);
    cpa16(&Asf[0][l_row1 * SSTR + l_q1 * 4], Ar1);
    cpa16(&Wsf[0][l_row1 * SSTR + l_q1 * 4], Wr1);
    CPA_COMMIT();

    int nt = K >> 4;
    for (int kt = 0; kt < nt; kt++) {
        int cur = kt & 1;
        CPA_WAIT0();
        __syncthreads();     // single sync per iter: orders completion AND buffer reuse
        if (kt + 1 < nt) {
            int k0 = (kt + 1) << 4;
            int nx = cur ^ 1;
            cpa16(&Asf[nx][l_row0 * SSTR + l_q0 * 4], Ar0 + k0);
            cpa16(&Wsf[nx][l_row0 * SSTR + l_q0 * 4], Wr0 + k0);
            cpa16(&Asf[nx][l_row1 * SSTR + l_q1 * 4], Ar1 + k0);
            cpa16(&Wsf[nx][l_row1 * SSTR + l_q1 * 4], Wr1 + k0);
            CPA_COMMIT();
        }
        const uint32_t* As = (const uint32_t*)Asf[cur];
        const uint32_t* Ws = (const uint32_t*)Wsf[cur];
#pragma unroll
        for (int kf = 0; kf < 2; kf++) {
            int kb = kf * 8;
            uint32_t a[4][4], b[4][2];
#pragma unroll
            for (int mf = 0; mf < 4; mf++) {
                int rb = (wm * 64 + mf * 16) * SSTR + kb;
                a[mf][0] = As[rb + grp * SSTR + qid];
                a[mf][1] = As[rb + (grp + 8) * SSTR + qid];
                a[mf][2] = As[rb + grp * SSTR + qid + 4];
                a[mf][3] = As[rb + (grp + 8) * SSTR + qid + 4];
            }
#pragma unroll
            for (int nf = 0; nf < 4; nf++) {
                int cb = (wn * 32 + nf * 8 + grp) * SSTR + kb;
                b[nf][0] = Ws[cb + qid];
                b[nf][1] = Ws[cb + qid + 4];
            }
#pragma unroll
            for (int mf = 0; mf < 4; mf++)
#pragma unroll
                for (int nf = 0; nf < 4; nf++) {
                    asm volatile(
                        "mma.sync.aligned.m16n8k8.row.col.f32.tf32.tf32.f32 "
                        "{%0,%1,%2,%3}, {%4,%5,%6,%7}, {%8,%9}, {%0,%1,%2,%3};\n"
                        : "+f"(acc[mf][nf][0]), "+f"(acc[mf][nf][1]),
                          "+f"(acc[mf][nf][2]), "+f"(acc[mf][nf][3])
                        : "r"(a[mf][0]), "r"(a[mf][1]), "r"(a[mf][2]), "r"(a[mf][3]),
                          "r"(b[nf][0]), "r"(b[nf][1]));
                }
        }
    }

#pragma unroll
    for (int nf = 0; nf < 4; nf++) {
        int col = bn + wn * 32 + nf * 8 + qid * 2;
        float b0 = bias1[col], b1 = bias1[col + 1];
        if (bias2) { b0 += bias2[col]; b1 += bias2[col + 1]; }
#pragma unroll
        for (int mf = 0; mf < 4; mf++) {
            int row = bm + wm * 64 + mf * 16 + grp;
            float v0 = acc[mf][nf][0] + b0, v1 = acc[mf][nf][1] + b1;
            float v2 = acc[mf][nf][2] + b0, v3 = acc[mf][nf][3] + b1;
            if (flags & 1) {
                v0 = fmaxf(v0, 0.f); v1 = fmaxf(v1, 0.f);
                v2 = fmaxf(v2, 0.f); v3 = fmaxf(v3, 0.f);
            }
            if (flags & 2) {
                v0 = f2tff(v0); v1 = f2tff(v1); v2 = f2tff(v2); v3 = f2tff(v3);
            }
            *(float2*)&C[(size_t)row * ldc + col] = make_float2(v0, v1);
            *(float2*)&C[(size_t)(row + 8) * ldc + col] = make_float2(v2, v3);
        }
    }
}

// ======== 4x4-tile 32x32xK block matmul helpers (persistent loops) ========
#define SAC(kg, r, b) sac[((kg) * 32 + (r)) * 33 + (b)]

__device__ __forceinline__ void mm4x4(const float (&Ws)[4][32][36], const float (&Xs)[4][32][36],
                                      int kg, int rx, int bx, float (&acc)[4][4]) {
#pragma unroll
    for (int kq = 0; kq < 8; kq++) {
        float4 w0 = *(const float4*)&Ws[kg][rx][kq * 4];
        float4 w1 = *(const float4*)&Ws[kg][rx + 8][kq * 4];
        float4 w2 = *(const float4*)&Ws[kg][rx + 16][kq * 4];
        float4 w3 = *(const float4*)&Ws[kg][rx + 24][kq * 4];
        float4 x0 = *(const float4*)&Xs[kg][bx][kq * 4];
        float4 x1 = *(const float4*)&Xs[kg][bx + 8][kq * 4];
        float4 x2 = *(const float4*)&Xs[kg][bx + 16][kq * 4];
        float4 x3 = *(const float4*)&Xs[kg][bx + 24][kq * 4];
        float4 wv[4] = {w0, w1, w2, w3};
        float4 xv[4] = {x0, x1, x2, x3};
#pragma unroll
        for (int i = 0; i < 4; i++)
#pragma unroll
            for (int j = 0; j < 4; j++)
                acc[i][j] += wv[i].x * xv[j].x + wv[i].y * xv[j].y
                           + wv[i].z * xv[j].z + wv[i].w * xv[j].w;
    }
}

// ---------------- persistent encoder loop (R14 structure) ----------------
__global__ void __launch_bounds__(256) k_enc_loop(const float* __restrict__ Whh_f,
                                                  const float* __restrict__ Whh_b) {
    __shared__ float Ws[4][32][36];
    __shared__ float Xs[4][32][36];
    __shared__ float c_s[8][32];
    float* sac = &Ws[0][0][0];
    int tid = threadIdx.x, bid = blockIdx.x;

    for (int i = bid * 256 + tid; i < 2 * Bq * Hq; i += NB * 256)
        ((float*)g_h[0])[i] = 0.f;
    c_s[tid >> 5][tid & 31] = 0.f;
    gridbar();

    bool active = bid < 128;
    int d = bid >> 6;
    int u0 = (bid & 63) * 8;
    const float* W = d ? Whh_b : Whh_f;
    const float* X = d ? g_Xb : g_Xf;
    int kg = tid >> 6, t64 = tid & 63, rx = t64 >> 3, bx = t64 & 7;

    for (int s = 0; s < Sq; s++) {
        int slot = s & 1;
        if (active) {
            float acc[4][4];
#pragma unroll
            for (int i = 0; i < 4; i++)
#pragma unroll
                for (int j = 0; j < 4; j++) acc[i][j] = 0.f;

            for (int c = 0; c < 4; c++) {
#pragma unroll
                for (int i = 0; i < 4; i++) {
                    int idx = tid * 4 + i;
                    int kgs = idx >> 8, r = (idx >> 3) & 31, q = idx & 7;
                    int k = kgs * 128 + c * 32 + q * 4;
                    int grow = ((r >> 3) << 9) + u0 + (r & 7);
                    *(float4*)&Ws[kgs][r][q * 4] = *(const float4*)(W + (size_t)grow * Hq + k);
                    *(float4*)&Xs[kgs][r][q * 4] = __ldcg((const float4*)&g_h[slot][d][r][k]);
                }
                __syncthreads();
                mm4x4(Ws, Xs, kg, rx, bx, acc);
                __syncthreads();
            }
#pragma unroll
            for (int i = 0; i < 4; i++)
#pragma unroll
                for (int j = 0; j < 4; j++)
                    SAC(kg, rx + 8 * i, bx + 8 * j) = acc[i][j];
            __syncthreads();
            int uj = tid >> 5, b = tid & 31;
            int seff = d ? (Sq - 1 - s) : s;
            const float* Xp = X + ((size_t)seff * Bq + b) * G4;
            int u = u0 + uj;
            float gi = Xp[u], gf = Xp[512 + u], gg = Xp[1024 + u], go = Xp[1536 + u];
#pragma unroll
            for (int k2 = 0; k2 < 4; k2++) {
                gi += SAC(k2, uj, b);
                gf += SAC(k2, 8 + uj, b);
                gg += SAC(k2, 16 + uj, b);
                go += SAC(k2, 24 + uj, b);
            }
            float c = c_s[uj][b];
            c = sigf(gf) * c + sigf(gi) * tanhf(gg);
            float h = sigf(go) * tanhf(c);
            c_s[uj][b] = c;
            g_h[slot ^ 1][d][b][u] = h;
            g_encout[b][seff][(d << 9) + u] = f2tff(h);   // feeds P GEMM only -> tf32
            g_encT[b][(d << 9) + u][seff] = h;
            if (d == 0 && s == Sq - 1) {
                g_hd[0][b][u] = h;
                g_cd[b][u] = c;
            }
        }
        gridbar();
    }
}

// ---------------- persistent decoder loop (R14 structure, 4 barriers/step) ----------------
__global__ void __launch_bounds__(256) k_dec_loop(
    const float* __restrict__ att1_W, const float* __restrict__ att2_W,
    const float* __restrict__ dWih, const float* __restrict__ dWhh)
{
    __shared__ float Ws[4][32][36];
    __shared__ float Xs[4][32][36];
    __shared__ float a2s[H3];
    __shared__ float sw[128];
    __shared__ float c_s[8][32];
    float* sac = &Ws[0][0][0];
    int tid = threadIdx.x, bid = blockIdx.x;
    int kg = tid >> 6, t64 = tid & 63, rx = t64 >> 3, bx = t64 & 7;

    for (int j = tid; j < H3; j += 256) a2s[j] = att2_W[j];
    if (bid < 64) {
        int uj = tid >> 5, b = tid & 31;
        c_s[uj][b] = __ldcg(&g_cd[b][(bid << 3) + uj]);
    }
    gridbar();

    for (int t = 0; t < Tq; t++) {
        int slot = t & 1;
        // ---- phase A: Qp[kh][b][j] partials = h @ att1_W[:,1024:]^T (k-split 2) ----
        if (bid < 96) {
            int kh = bid >= 48;
            int j0 = (bid % 48) * 32;
            float acc[4][4];
#pragma unroll
            for (int i = 0; i < 4; i++)
#pragma unroll
                for (int j = 0; j < 4; j++) acc[i][j] = 0.f;
            for (int c = 0; c < 2; c++) {
#pragma unroll
                for (int i = 0; i < 4; i++) {
                    int idx = tid * 4 + i;
                    int kgs = idx >> 8, r = (idx >> 3) & 31, q = idx & 7;
                    int k = kh * 256 + kgs * 64 + c * 32 + q * 4;
                    *(float4*)&Ws[kgs][r][q * 4] =
                        *(const float4*)(att1_W + (size_t)(j0 + r) * H3 + H2 + k);
                    *(float4*)&Xs[kgs][r][q * 4] = __ldcg((const float4*)&g_hd[slot][r][k]);
                }
                __syncthreads();
                mm4x4(Ws, Xs, kg, rx, bx, acc);
                __syncthreads();
            }
#pragma unroll
            for (int i = 0; i < 4; i++)
#pragma unroll
                for (int j = 0; j < 4; j++)
                    SAC(kg, rx + 8 * i, bx + 8 * j) = acc[i][j];
            __syncthreads();
#pragma unroll
            for (int i = 0; i < 4; i++) {
                int cell = i * 256 + tid;
                int r = cell >> 5, b = cell & 31;
                g_Qp[kh][b][j0 + r] = SAC(0, r, b) + SAC(1, r, b) + SAC(2, r, b) + SAC(3, r, b);
            }
        }
        gridbar();
        // ---- phase BC: scores + softmax + ctx, one block per batch ----
        if (bid < 32) {
            int b = bid;
            int warp = tid >> 5, lane = tid & 31;
            for (int s = warp; s < Sq; s += 8) {
                const float* Pp = g_P + ((size_t)b * Sq + s) * H3;
                float acc = 0.f;
#pragma unroll
                for (int jj = 0; jj < 12; jj++) {
                    int j = jj * 128 + lane * 4;
                    float4 p = *(const float4*)(Pp + j);
                    float4 q0 = __ldcg((const float4*)&g_Qp[0][b][j]);
                    float4 q1 = __ldcg((const float4*)&g_Qp[1][b][j]);
                    float4 a = *(const float4*)&a2s[j];
                    acc += fmaxf(p.x + q0.x + q1.x, 0.f) * a.x
                         + fmaxf(p.y + q0.y + q1.y, 0.f) * a.y
                         + fmaxf(p.z + q0.z + q1.z, 0.f) * a.z
                         + fmaxf(p.w + q0.w + q1.w, 0.f) * a.w;
                }
#pragma unroll
                for (int o = 16; o; o >>= 1) acc += __shfl_xor_sync(0xffffffffu, acc, o);
                if (!lane) sw[s] = acc;
            }
            __syncthreads();
            float mx = -1e30f;
#pragma unroll 4
            for (int i = 0; i < 100; i++) mx = fmaxf(mx, sw[i]);
            float ev = (tid < 100) ? __expf(sw[tid] - mx) : 0.f;
            __syncthreads();
            if (tid < 100) sw[tid] = ev;
            __syncthreads();
            float sum = 0.f;
#pragma unroll 4
            for (int i = 0; i < 100; i++) sum += sw[i];
            float inv = 1.f / sum;
#pragma unroll
            for (int kk = 0; kk < 4; kk++) {
                int k = kk * 256 + tid;
                const float* eT = &g_encT[b][k][0];
                float acc = 0.f;
#pragma unroll
                for (int s4 = 0; s4 < 100; s4 += 4) {
                    float4 e4 = *(const float4*)(eT + s4);
                    acc += sw[s4] * e4.x + sw[s4 + 1] * e4.y
                         + sw[s4 + 2] * e4.z + sw[s4 + 3] * e4.w;
                }
                g_ctxs[t][b][k] = acc * inv;
            }
        }
        gridbar();
        // ---- phase D: gate GEMM over K=1536 (ctx 1024 | h 512), k-split 2 ----
        if (bid < 128) {
            int kh = bid >> 6;
            int u0 = (bid & 63) * 8;
            float acc[4][4];
#pragma unroll
            for (int i = 0; i < 4; i++)
#pragma unroll
                for (int j = 0; j < 4; j++) acc[i][j] = 0.f;
            for (int c = 0; c < 6; c++) {
#pragma unroll
                for (int i = 0; i < 4; i++) {
                    int idx = tid * 4 + i;
                    int kgs = idx >> 8, r = (idx >> 3) & 31, q = idx & 7;
                    int k = kh * 768 + kgs * 192 + c * 32 + q * 4;
                    int grow = ((r >> 3) << 9) + u0 + (r & 7);
                    if (k < 1024) {
                        *(float4*)&Ws[kgs][r][q * 4] =
                            *(const float4*)(dWih + (size_t)grow * H3 + 512 + k);
                        *(float4*)&Xs[kgs][r][q * 4] = __ldcg((const float4*)&g_ctxs[t][r][k]);
                    } else {
                        *(float4*)&Ws[kgs][r][q * 4] =
                            *(const float4*)(dWhh + (size_t)grow * Hq + (k - 1024));
                        *(float4*)&Xs[kgs][r][q * 4] =
                            __ldcg((const float4*)&g_hd[slot][r][k - 1024]);
                    }
                }
                __syncthreads();
                mm4x4(Ws, Xs, kg, rx, bx, acc);
                __syncthreads();
            }
#pragma unroll
            for (int i = 0; i < 4; i++)
#pragma unroll
                for (int j = 0; j < 4; j++)
                    SAC(kg, rx + 8 * i, bx + 8 * j) = acc[i][j];
            __syncthreads();
#pragma unroll
            for (int i = 0; i < 4; i++) {
                int cell = i * 256 + tid;
                int r = cell >> 5, b = cell & 31;
                int gr = ((r >> 3) << 9) + u0 + (r & 7);
                g_gpart[kh][gr][b] = SAC(0, r, b) + SAC(1, r, b) + SAC(2, r, b) + SAC(3, r, b);
            }
        }
        gridbar();
        // ---- phase E: combine partials + LSTM update ----
        if (bid < 64) {
            int uj = tid >> 5, b = tid & 31;
            int u = (bid << 3) + uj;
            const float* Xp = g_Xdec + ((size_t)t * Bq + b) * G4;
            float gi = __ldcg(&g_gpart[0][u][b])        + __ldcg(&g_gpart[1][u][b])        + Xp[u];
            float gf = __ldcg(&g_gpart[0][512 + u][b])  + __ldcg(&g_gpart[1][512 + u][b])  + Xp[512 + u];
            float gg = __ldcg(&g_gpart[0][1024 + u][b]) + __ldcg(&g_gpart[1][1024 + u][b]) + Xp[1024 + u];
            float go = __ldcg(&g_gpart[0][1536 + u][b]) + __ldcg(&g_gpart[1][1536 + u][b]) + Xp[1536 + u];
            float c = c_s[uj][b];
            c = sigf(gf) * c + sigf(gi) * tanhf(gg);
            float h = sigf(go) * tanhf(c);
            c_s[uj][b] = c;
            g_hd[slot ^ 1][b][u] = h;
            g_decs[t][b][u] = h;
        }
        gridbar();
    }
}

// ---------------- classifier input pack (converts to tf32 for cls1 GEMM) ----------------
__global__ void k_pack() {
    int m = blockIdx.x;            // m = b*T + t
    int b = m / Tq, t = m % Tq;
    int tid = threadIdx.x;         // 128
    float4* dst = (float4*)(g_clsin + (size_t)m * 2048);
    float4 v0 = ((const float4*)&g_temb[b][t][0])[tid];
    float4 v1 = ((const float4*)&g_ctxs[t][b][0])[tid];
    float4 v2 = ((const float4*)&g_ctxs[t][b][0])[128 + tid];
    float4 v3 = ((const float4*)&g_decs[t][b][0])[tid];
    dst[tid]       = make_float4(f2tff(v0.x), f2tff(v0.y), f2tff(v0.z), f2tff(v0.w));
    dst[128 + tid] = make_float4(f2tff(v1.x), f2tff(v1.y), f2tff(v1.z), f2tff(v1.w));
    dst[256 + tid] = make_float4(f2tff(v2.x), f2tff(v2.y), f2tff(v2.z), f2tff(v2.w));
    dst[384 + tid] = make_float4(f2tff(v3.x), f2tff(v3.y), f2tff(v3.z), f2tff(v3.w));
}

// ---------------- host ----------------
extern "C" void kernel_launch(void* const* d_in, const int* in_sizes, int n_in,
                              void* d_out, int out_size) {
    (void)in_sizes; (void)n_in; (void)out_size;
    const int*   src       = (const int*)d_in[0];
    const int*   tgt       = (const int*)d_in[1];
    const float* src_emb   = (const float*)d_in[2];
    const float* tgt_emb   = (const float*)d_in[3];
    const float* eWih_f    = (const float*)d_in[4];
    const float* eWhh_f    = (const float*)d_in[5];
    const float* ebih_f    = (const float*)d_in[6];
    const float* ebhh_f    = (const float*)d_in[7];
    const float* eWih_b    = (const float*)d_in[8];
    const float* eWhh_b    = (const float*)d_in[9];
    const float* ebih_b    = (const float*)d_in[10];
    const float* ebhh_b    = (const float*)d_in[11];
    const float* dWih      = (const float*)d_in[12];
    const float* dWhh      = (const float*)d_in[13];
    const float* dbih      = (const float*)d_in[14];
    const float* dbhh      = (const float*)d_in[15];
    const float* att1_W    = (const float*)d_in[16];
    const float* att1_b    = (const float*)d_in[17];
    const float* att2_W    = (const float*)d_in[18];
    const float* cls1_W    = (const float*)d_in[20];
    const float* cls1_b    = (const float*)d_in[21];
    const float* cls2_W    = (const float*)d_in[22];
    const float* cls2_b    = (const float*)d_in[23];
    float* out = (float*)d_out;

    float *p_xsrc, *p_Xf, *p_Xb, *p_encout, *p_P, *p_temb_tb, *p_Xdec, *p_clsin, *p_hid;
    float *p_wfT, *p_wbT, *p_dwT, *p_a1T, *p_c1T, *p_c2T;
    cudaGetSymbolAddress((void**)&p_xsrc, g_xsrc);
    cudaGetSymbolAddress((void**)&p_Xf, g_Xf);
    cudaGetSymbolAddress((void**)&p_Xb, g_Xb);
    cudaGetSymbolAddress((void**)&p_encout, g_encout);
    cudaGetSymbolAddress((void**)&p_P, g_P);
    cudaGetSymbolAddress((void**)&p_temb_tb, g_temb_tb);
    cudaGetSymbolAddress((void**)&p_Xdec, g_Xdec);
    cudaGetSymbolAddress((void**)&p_clsin, g_clsin);
    cudaGetSymbolAddress((void**)&p_hid, g_hid);
    cudaGetSymbolAddress((void**)&p_wfT, g_wfT);
    cudaGetSymbolAddress((void**)&p_wbT, g_wbT);
    cudaGetSymbolAddress((void**)&p_dwT, g_dwT);
    cudaGetSymbolAddress((void**)&p_a1T, g_a1T);
    cudaGetSymbolAddress((void**)&p_c1T, g_c1T);
    cudaGetSymbolAddress((void**)&p_c2T, g_c2T);

    // weight conversions (once per launch, pure bandwidth)
    k_conv<<<1024, 256>>>(p_wfT, eWih_f, Eq, Eq);
    k_conv<<<1024, 256>>>(p_wbT, eWih_b, Eq, Eq);
    k_conv<<<1024, 256>>>(p_dwT, dWih, Eq, H3);          // first 512 cols
    k_conv<<<1536, 256>>>(p_a1T, att1_W, H2, H3);        // first 1024 cols
    k_conv<<<2048, 256>>>(p_c1T, cls1_W, 2048, 2048);
    k_conv<<<32000, 256>>>(p_c2T, cls2_W, H2, H2);

    k_gather_src<<<Sq * Bq, 128>>>(src, src_emb);
    k_gather_tgt<<<Bq * Tq, 128>>>(tgt, tgt_emb);

    // encoder input gates
    k_mma<<<dim3(25, 16), 256>>>(p_xsrc, Eq, p_wfT, Eq, ebih_f, ebhh_f,
                                 p_Xf, G4, Sq * Bq, G4, Eq, 0);
    k_mma<<<dim3(25, 16), 256>>>(p_xsrc, Eq, p_wbT, Eq, ebih_b, ebhh_b,
                                 p_Xb, G4, Sq * Bq, G4, Eq, 0);

    // persistent encoder (100 steps, 1 launch)
    k_enc_loop<<<NB, 256>>>(eWhh_f, eWhh_b);

    // attention layer-1 enc part (hoisted)
    k_mma<<<dim3(25, 12), 256>>>(p_encout, H2, p_a1T, H2, att1_b, (const float*)nullptr,
                                 p_P, H3, Bq * Sq, H3, H2, 0);

    // decoder input gates (embedding part)
    k_mma<<<dim3(25, 16), 256>>>(p_temb_tb, Eq, p_dwT, Eq, dbih, dbhh,
                                 p_Xdec, G4, Tq * Bq, G4, Eq, 0);

    // persistent decoder (100 steps, 1 launch)
    k_dec_loop<<<NB, 256>>>(att1_W, att2_W, dWih, dWhh);

    k_pack<<<Bq * Tq, 128>>>();

    // classifier
    k_mma<<<dim3(25, 8), 256>>>(p_clsin, 2048, p_c1T, 2048, cls1_b, (const float*)nullptr,
                                p_hid, H2, Bq * Tq, H2, 2048, 3);
    k_mma<<<dim3(25, 250), 256>>>(p_hid, H2, p_c2T, H2, cls2_b, (const float*)nullptr,
                                  out, VTq, Bq * Tq, VTq, H2, 0);
}